// round 2
// baseline (speedup 1.0000x reference)
#include <cuda_runtime.h>
#include <cstdint>
#include <cstddef>

// Problem constants (fixed shapes: x[16,2048,512], embed_weight[4096,512])
#define M_ROWS 32768
#define DIM    512
#define NCODES 4096

// GEMM-argmin tiling
#define BM 64
#define BN 128
#define BK 32
#define NT_TILES (NCODES / BN)   // 32
#define KT_TILES (DIM / BK)      // 16
#define TPB 512

// SMEM layout (float offsets)
#define OFF_XST 0                         // xsT[512][64]  (transposed x tile)
#define OFF_WS  (DIM * BM)                // ws[2][32][128] double-buffered w tile
#define OFF_AS  (OFF_WS + 2 * BK * BN)    // a_s[64]
#define OFF_RV  (OFF_AS + 64)             // redv[64][33] (also double scratch)
#define OFF_RI  (OFF_RV + BM * 33)        // redi[64][33]
#define SMEM_FLOATS (OFF_RI + BM * 33)    // 45248 floats = 180992 bytes

// ---------------- device scratch (no allocations allowed) ----------------
__device__ float  g_whatT[DIM * NCODES];  // normalized codebook, [k][n], 8 MB
__device__ float  g_c[NCODES];            // c[n] = fp32(sum(w_hat^2))
__device__ int    g_idx[M_ROWS];          // argmin index per row
__device__ double g_part[M_ROWS];         // per-row partial sums for diff

// ---------------- packed f32x2 helpers (PTX-only on sm_103a) -------------
__device__ __forceinline__ unsigned long long pack2(float x, float y) {
    unsigned long long r;
    asm("mov.b64 %0, {%1, %2};" : "=l"(r)
        : "r"(__float_as_uint(x)), "r"(__float_as_uint(y)));
    return r;
}
__device__ __forceinline__ unsigned long long dup2(float x) {
    unsigned long long r;
    asm("mov.b64 %0, {%1, %1};" : "=l"(r) : "r"(__float_as_uint(x)));
    return r;
}
__device__ __forceinline__ void ffma2(unsigned long long& d,
                                      unsigned long long a,
                                      unsigned long long b) {
    asm("fma.rn.f32x2 %0, %1, %2, %0;" : "+l"(d) : "l"(a), "l"(b));
}
__device__ __forceinline__ void unpack2(unsigned long long v, float& x, float& y) {
    unsigned lo, hi;
    asm("mov.b64 {%0, %1}, %2;" : "=r"(lo), "=r"(hi) : "l"(v));
    x = __uint_as_float(lo);
    y = __uint_as_float(hi);
}
__device__ __forceinline__ void cpa16(void* dst_smem, const void* src) {
    unsigned d = (unsigned)__cvta_generic_to_shared(dst_smem);
    asm volatile("cp.async.cg.shared.global [%0], [%1], 16;" :: "r"(d), "l"(src));
}
__device__ __forceinline__ void cpa_commit() { asm volatile("cp.async.commit_group;"); }
__device__ __forceinline__ void cpa_wait0()  { asm volatile("cp.async.wait_group 0;"); }

// =====================================================================
// Kernel 1: normalize codebook -> g_whatT [k][n]; c[n] = fp32(sum w_hat^2)
// norm computed in double then rounded (best estimate of ref's fp32 value);
// the division w/norm uses IEEE fp32 div exactly like the reference.
// grid = 4096, block = 128 (4 elements per thread)
// =====================================================================
__global__ void prep_kernel(const float* __restrict__ ew) {
    __shared__ double sred[128];
    const int n = blockIdx.x;
    const int t = threadIdx.x;

    float4 v = reinterpret_cast<const float4*>(ew + (size_t)n * DIM)[t];
    double s = (double)v.x * v.x + (double)v.y * v.y +
               (double)v.z * v.z + (double)v.w * v.w;
    sred[t] = s;
    __syncthreads();
    for (int o = 64; o; o >>= 1) {
        if (t < o) sred[t] += sred[t + o];
        __syncthreads();
    }
    const float norm = sqrtf((float)sred[0]);
    __syncthreads();  // protect sred before reuse

    const float w0 = __fdiv_rn(v.x, norm);
    const float w1 = __fdiv_rn(v.y, norm);
    const float w2 = __fdiv_rn(v.z, norm);
    const float w3 = __fdiv_rn(v.w, norm);

    g_whatT[(size_t)(4 * t + 0) * NCODES + n] = w0;
    g_whatT[(size_t)(4 * t + 1) * NCODES + n] = w1;
    g_whatT[(size_t)(4 * t + 2) * NCODES + n] = w2;
    g_whatT[(size_t)(4 * t + 3) * NCODES + n] = w3;

    double c = (double)w0 * w0 + (double)w1 * w1 +
               (double)w2 * w2 + (double)w3 * w3;
    sred[t] = c;
    __syncthreads();
    for (int o = 64; o; o >>= 1) {
        if (t < o) sred[t] += sred[t + o];
        __syncthreads();
    }
    if (t == 0) g_c[n] = (float)sred[0];
}

// =====================================================================
// Kernel 2: fused GEMM + argmin.
// One CTA per 64 rows. Full-K x tile resident in SMEM (transposed),
// codebook streamed in [32 k][128 n] tiles via double-buffered cp.async.
// Inner loop: packed f32x2 FMA, 4x4 per-thread microtile.
// dist replication: d = fl( fl(a - fl(2*b)) + c ), first-index tie-break.
// =====================================================================
__global__ void __launch_bounds__(TPB, 1) argmin_kernel(const float* __restrict__ x) {
    extern __shared__ float sm[];
    float* xsT  = sm + OFF_XST;
    float* ws   = sm + OFF_WS;
    float* a_s  = sm + OFF_AS;
    float* redv = sm + OFF_RV;
    int*   redi = reinterpret_cast<int*>(sm + OFF_RI);

    const int tid = threadIdx.x;
    const int bid = blockIdx.x;
    const float* xblk = x + (size_t)bid * BM * DIM;

    // ---- load x (64 rows x 512 k) into xsT[k][m] via conflict-free staging ----
    {
        float* stg = ws;                 // staging [64][33] (aliases w buffer)
        const int tr  = tid >> 3;        // row 0..63
        const int tk  = (tid & 7) * 4;   // k-in-chunk 0..28
        const int tm2 = tid & 63;        // transpose-read row
        const int tk2 = (tid >> 6) * 4;  // transpose-read k base
        for (int kc = 0; kc < KT_TILES; kc++) {
            float4 v = *reinterpret_cast<const float4*>(xblk + (size_t)tr * DIM + kc * BK + tk);
            __syncthreads();  // previous chunk's readers done
            stg[tr * 33 + tk + 0] = v.x;
            stg[tr * 33 + tk + 1] = v.y;
            stg[tr * 33 + tk + 2] = v.z;
            stg[tr * 33 + tk + 3] = v.w;
            __syncthreads();
            const int kb = kc * BK + tk2;
            xsT[(kb + 0) * BM + tm2] = stg[tm2 * 33 + tk2 + 0];
            xsT[(kb + 1) * BM + tm2] = stg[tm2 * 33 + tk2 + 1];
            xsT[(kb + 2) * BM + tm2] = stg[tm2 * 33 + tk2 + 2];
            xsT[(kb + 3) * BM + tm2] = stg[tm2 * 33 + tk2 + 3];
        }
        __syncthreads();
    }

    // ---- a[m] = fp32(double sum x^2) per row (exact -> rounded once) ----
    if (tid < 256) {
        const int m = tid >> 2, p = tid & 3;
        const int k0 = p * 128;
        double s0 = 0.0, s1 = 0.0;
        for (int k = 0; k < 128; k += 2) {
            float u0 = xsT[(k0 + k) * BM + m];
            float u1 = xsT[(k0 + k + 1) * BM + m];
            s0 += (double)u0 * u0;
            s1 += (double)u1 * u1;
        }
        reinterpret_cast<double*>(redv)[m * 4 + p] = s0 + s1;
    }
    __syncthreads();
    if (tid < 64) {
        const double* dp = reinterpret_cast<const double*>(redv);
        a_s[tid] = (float)(dp[tid * 4] + dp[tid * 4 + 1] + dp[tid * 4 + 2] + dp[tid * 4 + 3]);
    }
    __syncthreads();

    // ---- main fused GEMM + argmin ----
    const int tm = tid & 15;   // 16 m-groups of 4 rows
    const int tn = tid >> 4;   // 32 n-groups of 4 cols
    const float av0 = a_s[tm * 4 + 0];
    const float av1 = a_s[tm * 4 + 1];
    const float av2 = a_s[tm * 4 + 2];
    const float av3 = a_s[tm * 4 + 3];

    float minv[4];
    int   mini[4];
#pragma unroll
    for (int i = 0; i < 4; i++) { minv[i] = __int_as_float(0x7f800000); mini[i] = 0; }

    const int g0 = tid * 2;  // this thread's two 16B granules per w ktile

    for (int nt = 0; nt < NT_TILES; nt++) {
        // prefetch ktile 0 into buffer 0
#pragma unroll
        for (int j = 0; j < 2; j++) {
            const int g = g0 + j;
            const int r = g >> 5;
            const int c4 = (g & 31) * 4;
            cpa16(&ws[r * BN + c4], g_whatT + (size_t)r * NCODES + nt * BN + c4);
        }
        cpa_commit();

        unsigned long long acc[2][4];
#pragma unroll
        for (int p = 0; p < 2; p++)
#pragma unroll
            for (int j = 0; j < 4; j++) acc[p][j] = 0ull;

        for (int kt = 0; kt < KT_TILES; kt++) {
            cpa_wait0();
            __syncthreads();
            if (kt + 1 < KT_TILES) {
                const int kb = (kt + 1) * BK;
                const int b  = (kt + 1) & 1;
#pragma unroll
                for (int j = 0; j < 2; j++) {
                    const int g = g0 + j;
                    const int r = g >> 5;
                    const int c4 = (g & 31) * 4;
                    cpa16(&ws[b * BK * BN + r * BN + c4],
                          g_whatT + (size_t)(kb + r) * NCODES + nt * BN + c4);
                }
                cpa_commit();
            }
            const float* wb = ws + (kt & 1) * BK * BN;
            const float* xk = xsT + kt * BK * BM;
#pragma unroll
            for (int k = 0; k < BK; k++) {
                float4 a4 = *reinterpret_cast<const float4*>(xk + k * BM + tm * 4);
                float4 b4 = *reinterpret_cast<const float4*>(wb + k * BN + tn * 4);
                unsigned long long a01 = pack2(a4.x, a4.y);
                unsigned long long a23 = pack2(a4.z, a4.w);
                unsigned long long d0 = dup2(b4.x), d1 = dup2(b4.y);
                unsigned long long d2 = dup2(b4.z), d3 = dup2(b4.w);
                ffma2(acc[0][0], a01, d0); ffma2(acc[1][0], a23, d0);
                ffma2(acc[0][1], a01, d1); ffma2(acc[1][1], a23, d1);
                ffma2(acc[0][2], a01, d2); ffma2(acc[1][2], a23, d2);
                ffma2(acc[0][3], a01, d3); ffma2(acc[1][3], a23, d3);
            }
        }

        // epilogue: dist = fl(fl(a - 2b) + c), running min (first index wins)
        const float4 cv = *reinterpret_cast<const float4*>(g_c + nt * BN + tn * 4);
        const float cva[4] = {cv.x, cv.y, cv.z, cv.w};
        const int nbase = nt * BN + tn * 4;
#pragma unroll
        for (int p = 0; p < 2; p++) {
            const float a0 = (p == 0) ? av0 : av2;
            const float a1 = (p == 0) ? av1 : av3;
#pragma unroll
            for (int j = 0; j < 4; j++) {
                float bx, by;
                unpack2(acc[p][j], bx, by);
                const float cj = cva[j];
                const float t0 = __fadd_rn(a0, -__fmul_rn(2.0f, bx));
                const float t1 = __fadd_rn(a1, -__fmul_rn(2.0f, by));
                const float dv0 = __fadd_rn(t0, cj);
                const float dv1 = __fadd_rn(t1, cj);
                const int r0 = p * 2, r1 = p * 2 + 1;
                if (dv0 < minv[r0]) { minv[r0] = dv0; mini[r0] = nbase + j; }
                if (dv1 < minv[r1]) { minv[r1] = dv1; mini[r1] = nbase + j; }
            }
        }
    }

    // ---- cross-thread reduction over the 32 n-groups ----
    __syncthreads();
#pragma unroll
    for (int i = 0; i < 4; i++) {
        redv[(tm * 4 + i) * 33 + tn] = minv[i];
        redi[(tm * 4 + i) * 33 + tn] = mini[i];
    }
    __syncthreads();
    if (tid < 64) {
        float bv = __int_as_float(0x7f800000);
        int   bi = NCODES;
        for (int t2 = 0; t2 < 32; t2++) {
            const float v = redv[tid * 33 + t2];
            const int  ix = redi[tid * 33 + t2];
            if (v < bv || (v == bv && ix < bi)) { bv = v; bi = ix; }
        }
        g_idx[bid * BM + tid] = bi;
    }
}

// =====================================================================
// Kernel 3: gather + straight-through output + per-row diff partials.
// out = fl( fl(q + fl(x + fl(q-x))) * 0.5 ) replicating ref fp32 ops.
// =====================================================================
__global__ void gather_kernel(const float* __restrict__ x,
                              const float* __restrict__ ew,
                              float* __restrict__ out) {
    __shared__ double sred[128];
    const int m = blockIdx.x;
    const int t = threadIdx.x;
    const int idx = g_idx[m];

    float4 q  = reinterpret_cast<const float4*>(ew + (size_t)idx * DIM)[t];
    float4 xv = reinterpret_cast<const float4*>(x  + (size_t)m * DIM)[t];

    float4 o;
    double s = 0.0;
    {
        float e, q1;
        e = __fadd_rn(q.x, -xv.x); q1 = __fadd_rn(xv.x, e);
        o.x = __fmul_rn(__fadd_rn(q.x, q1), 0.5f); s += (double)e * e;
        e = __fadd_rn(q.y, -xv.y); q1 = __fadd_rn(xv.y, e);
        o.y = __fmul_rn(__fadd_rn(q.y, q1), 0.5f); s += (double)e * e;
        e = __fadd_rn(q.z, -xv.z); q1 = __fadd_rn(xv.z, e);
        o.z = __fmul_rn(__fadd_rn(q.z, q1), 0.5f); s += (double)e * e;
        e = __fadd_rn(q.w, -xv.w); q1 = __fadd_rn(xv.w, e);
        o.w = __fmul_rn(__fadd_rn(q.w, q1), 0.5f); s += (double)e * e;
    }
    reinterpret_cast<float4*>(out)[(size_t)m * (DIM / 4) + t] = o;

    sred[t] = s;
    __syncthreads();
    for (int off = 64; off; off >>= 1) {
        if (t < off) sred[t] += sred[t + off];
        __syncthreads();
    }
    if (t == 0) g_part[m] = sred[0];
}

// =====================================================================
// Kernel 4: final diff reduction (double) -> single fp32 scalar
// =====================================================================
__global__ void diff_kernel(float* __restrict__ out, int write_scalar) {
    __shared__ double sred[256];
    const int t = threadIdx.x;
    double s = 0.0;
    for (int i = t; i < M_ROWS; i += 256) s += g_part[i];
    sred[t] = s;
    __syncthreads();
    for (int o = 128; o; o >>= 1) {
        if (t < o) sred[t] += sred[t + o];
        __syncthreads();
    }
    if (t == 0 && write_scalar)
        out[(size_t)M_ROWS * DIM] = (float)(sred[0] / (double)((size_t)M_ROWS * DIM));
}

// =====================================================================
extern "C" void kernel_launch(void* const* d_in, const int* in_sizes, int n_in,
                              void* d_out, int out_size) {
    const float* x  = (const float*)d_in[0];
    const float* ew = (const float*)d_in[1];
    // defensive: detect order by size (x has 16.7M elems, ew 2.1M)
    if (n_in >= 2 && in_sizes[0] == NCODES * DIM && in_sizes[1] == M_ROWS * DIM) {
        ew = (const float*)d_in[0];
        x  = (const float*)d_in[1];
    }
    float* out = (float*)d_out;

    cudaFuncSetAttribute(argmin_kernel,
                         cudaFuncAttributeMaxDynamicSharedMemorySize,
                         SMEM_FLOATS * (int)sizeof(float));

    prep_kernel<<<NCODES, 128>>>(ew);
    argmin_kernel<<<M_ROWS / BM, TPB, SMEM_FLOATS * sizeof(float)>>>(x);
    gather_kernel<<<M_ROWS, 128>>>(x, ew, out);
    const int write_scalar = (out_size > M_ROWS * DIM) ? 1 : 0;
    diff_kernel<<<1, 256>>>(out, write_scalar);
}

// round 5
// speedup vs baseline: 1.2927x; 1.2927x over previous
#include <cuda_runtime.h>
#include <cuda_bf16.h>
#include <cstdint>
#include <cstddef>

#define M_ROWS 32768
#define DIM    512
#define NCODES 4096

#define BM 128
#define BN 128
#define BK 32
#define NCH (DIM / BK)            // 16 chunks
#define NMT (M_ROWS / BM)         // 256
#define NNT (NCODES / BN)         // 32
#define TPB 256
#define THRESH 1e-3f

#define TILE_BYTES (128 * BK * 2)             // 8192 per plane tile
#define STAGE_BYTES (6 * TILE_BYTES)          // 49152
#define SMEM_BYTES (2 * STAGE_BYTES)          // 98304

// ---------------- device scratch (allocation is forbidden) ----------------
__device__ __align__(128) __nv_bfloat16 g_XA[(size_t)NMT * 3 * 128 * DIM]; // 96MB
__device__ __align__(128) __nv_bfloat16 g_WB[(size_t)NNT * 3 * 128 * DIM]; // 12MB
__device__ __align__(128) float g_whatT[DIM * NCODES];                     // 8MB [k][n]
__device__ float  g_a[M_ROWS];
__device__ float  g_c[NCODES];
__device__ int    g_idx[M_ROWS];
__device__ unsigned long long g_cand1[(size_t)M_ROWS * NNT];  // per (m,ntile) best key
__device__ float  g_cand2[(size_t)M_ROWS * NNT];              // per (m,ntile) 2nd value
__device__ int    g_list[M_ROWS];
__device__ int    g_cnt;
__device__ double g_diff;

// ---------------- PTX helpers (base sm_80 features only) ------------------
__device__ __forceinline__ uint32_t smem_u32(const void* p) {
    uint32_t a;
    asm("{ .reg .u64 t; cvta.to.shared.u64 t, %1; cvt.u32.u64 %0, t; }" : "=r"(a) : "l"(p));
    return a;
}
__device__ __forceinline__ void cpa16(uint32_t dst, const void* src) {
    asm volatile("cp.async.cg.shared.global [%0], [%1], 16;" :: "r"(dst), "l"(src));
}
__device__ __forceinline__ void cpa_commit() { asm volatile("cp.async.commit_group;"); }
template <int N>
__device__ __forceinline__ void cpa_wait() {
    asm volatile("cp.async.wait_group %0;" :: "n"(N));
}
__device__ __forceinline__ void ldsm_x4(uint32_t* r, uint32_t addr) {
    asm volatile("ldmatrix.sync.aligned.m8n8.x4.shared.b16 {%0,%1,%2,%3}, [%4];"
                 : "=r"(r[0]), "=r"(r[1]), "=r"(r[2]), "=r"(r[3]) : "r"(addr));
}
__device__ __forceinline__ void mma16816(float* d, const uint32_t* a, const uint32_t* b) {
    asm volatile(
        "mma.sync.aligned.m16n8k16.row.col.f32.bf16.bf16.f32 "
        "{%0,%1,%2,%3}, {%4,%5,%6,%7}, {%8,%9}, {%0,%1,%2,%3};"
        : "+f"(d[0]), "+f"(d[1]), "+f"(d[2]), "+f"(d[3])
        : "r"(a[0]), "r"(a[1]), "r"(a[2]), "r"(a[3]), "r"(b[0]), "r"(b[1]));
}
__device__ __forceinline__ uint32_t sw_off(int row, int g) {
    return (uint32_t)row * 64u + (uint32_t)((g ^ ((row >> 1) & 3)) << 4);
}
__device__ __forceinline__ void split3(float v, unsigned short& h1, unsigned short& h2,
                                       unsigned short& h3) {
    __nv_bfloat16 b1 = __float2bfloat16(v);
    float r1 = v - __bfloat162float(b1);
    __nv_bfloat16 b2 = __float2bfloat16(r1);
    float r2 = r1 - __bfloat162float(b2);
    __nv_bfloat16 b3 = __float2bfloat16(r2);
    h1 = __bfloat16_as_ushort(b1);
    h2 = __bfloat16_as_ushort(b2);
    h3 = __bfloat16_as_ushort(b3);
}
__device__ __forceinline__ uint2 pack4(const unsigned short* h) {
    uint2 q;
    q.x = (uint32_t)h[0] | ((uint32_t)h[1] << 16);
    q.y = (uint32_t)h[2] | ((uint32_t)h[3] << 16);
    return q;
}

// =====================================================================
// Prep W — byte-replicates R2's prep_kernel math (128 thr x 4 elems):
// norm = sqrtf((float)double_tree_sum), w = fdiv_rn, c = (float)double tree.
// Also writes whatT[k][n] fp32 and 3 bf16 planes (row-major [row][k]).
// =====================================================================
__global__ void prepw_kernel(const float* __restrict__ ew) {
    __shared__ double sred[128];
    const int n = blockIdx.x, t = threadIdx.x;

    float4 v = reinterpret_cast<const float4*>(ew + (size_t)n * DIM)[t];
    double s = (double)v.x * v.x + (double)v.y * v.y +
               (double)v.z * v.z + (double)v.w * v.w;
    sred[t] = s;
    __syncthreads();
    for (int o = 64; o; o >>= 1) { if (t < o) sred[t] += sred[t + o]; __syncthreads(); }
    const float norm = sqrtf((float)sred[0]);
    __syncthreads();

    const float w0 = __fdiv_rn(v.x, norm);
    const float w1 = __fdiv_rn(v.y, norm);
    const float w2 = __fdiv_rn(v.z, norm);
    const float w3 = __fdiv_rn(v.w, norm);

    g_whatT[(size_t)(4 * t + 0) * NCODES + n] = w0;
    g_whatT[(size_t)(4 * t + 1) * NCODES + n] = w1;
    g_whatT[(size_t)(4 * t + 2) * NCODES + n] = w2;
    g_whatT[(size_t)(4 * t + 3) * NCODES + n] = w3;

    double c = (double)w0 * w0 + (double)w1 * w1 +
               (double)w2 * w2 + (double)w3 * w3;
    sred[t] = c;
    __syncthreads();
    for (int o = 64; o; o >>= 1) { if (t < o) sred[t] += sred[t + o]; __syncthreads(); }
    if (t == 0) g_c[n] = (float)sred[0];

    float wv[4] = {w0, w1, w2, w3};
    unsigned short h1[4], h2[4], h3[4];
#pragma unroll
    for (int i = 0; i < 4; i++) split3(wv[i], h1[i], h2[i], h3[i]);

    const int ntile = n >> 7, row = n & 127;
    const size_t b0 = (((size_t)ntile * 3 + 0) * 128 + row) * DIM + 4 * t;
    const size_t b1 = (((size_t)ntile * 3 + 1) * 128 + row) * DIM + 4 * t;
    const size_t b2 = (((size_t)ntile * 3 + 2) * 128 + row) * DIM + 4 * t;
    *reinterpret_cast<uint2*>(g_WB + b0) = pack4(h1);
    *reinterpret_cast<uint2*>(g_WB + b1) = pack4(h2);
    *reinterpret_cast<uint2*>(g_WB + b2) = pack4(h3);
}

// =====================================================================
// Prep X — a[m] byte-replicates R2's order: 4 partials (k-range 128 each,
// dual stride-2 double accumulators), combined left-to-right, then (float).
// Also writes 3 bf16 planes; inits g_cnt / g_diff.
// =====================================================================
__global__ void prepx_kernel(const float* __restrict__ x) {
    __shared__ double part[4];
    const int m = blockIdx.x, t = threadIdx.x;
    const float* xr = x + (size_t)m * DIM;

    float4 v = reinterpret_cast<const float4*>(xr)[t];
    unsigned short h1[4], h2[4], h3[4];
    float vv[4] = {v.x, v.y, v.z, v.w};
#pragma unroll
    for (int i = 0; i < 4; i++) split3(vv[i], h1[i], h2[i], h3[i]);
    const int mtile = m >> 7, row = m & 127;
    const size_t b0 = (((size_t)mtile * 3 + 0) * 128 + row) * DIM + 4 * t;
    const size_t b1 = (((size_t)mtile * 3 + 1) * 128 + row) * DIM + 4 * t;
    const size_t b2 = (((size_t)mtile * 3 + 2) * 128 + row) * DIM + 4 * t;
    *reinterpret_cast<uint2*>(g_XA + b0) = pack4(h1);
    *reinterpret_cast<uint2*>(g_XA + b1) = pack4(h2);
    *reinterpret_cast<uint2*>(g_XA + b2) = pack4(h3);

    if (t < 4) {
        const int k0 = t * 128;
        double s0 = 0.0, s1 = 0.0;
        for (int k = 0; k < 128; k += 2) {
            float u0 = xr[k0 + k];
            float u1 = xr[k0 + k + 1];
            s0 += (double)u0 * u0;
            s1 += (double)u1 * u1;
        }
        part[t] = s0 + s1;
    }
    __syncthreads();
    if (t == 0) {
        g_a[m] = (float)(part[0] + part[1] + part[2] + part[3]);
        if (m == 0) { g_cnt = 0; g_diff = 0.0; }
    }
}

// =====================================================================
// HMMA GEMM + per-CTA top-2.  grid = NMT*NNT (ntile fastest), block 256.
// =====================================================================
__global__ void __launch_bounds__(TPB, 1) mma_topcand_kernel() {
    extern __shared__ unsigned char smraw[];
    const uint32_t sbase = smem_u32(smraw);

    const int tid = threadIdx.x;
    const int wid = tid >> 5, lid = tid & 31;
    const int wm = wid & 1, wn = wid >> 1;
    const int g = lid >> 2, tq = lid & 3;
    const int ntile = blockIdx.x & (NNT - 1);
    const int mtile = blockIdx.x >> 5;

    const __nv_bfloat16* Aab = g_XA + ((size_t)mtile * 3) * 128 * DIM;
    const __nv_bfloat16* Bab = g_WB + ((size_t)ntile * 3) * 128 * DIM;

    auto issue_chunk = [&](int kc, int st) {
        const uint32_t sdst = sbase + st * STAGE_BYTES;
#pragma unroll
        for (int t6 = 0; t6 < 6; t6++) {
            const __nv_bfloat16* src_base =
                (t6 < 3) ? (Aab + (size_t)t6 * 128 * DIM)
                         : (Bab + (size_t)(t6 - 3) * 128 * DIM);
#pragma unroll
            for (int j = 0; j < 2; j++) {
                const int q = tid + j * 256;
                const int row = q >> 2, gg = q & 3;
                cpa16(sdst + t6 * TILE_BYTES + sw_off(row, gg),
                      src_base + (size_t)row * DIM + kc * BK + gg * 8);
            }
        }
        cpa_commit();
    };

    float acc[4][4][4];
#pragma unroll
    for (int i = 0; i < 4; i++)
#pragma unroll
        for (int j = 0; j < 4; j++)
#pragma unroll
            for (int k = 0; k < 4; k++) acc[i][j][k] = 0.0f;

    issue_chunk(0, 0);
    const int PA[6] = {0, 0, 1, 1, 0, 2};
    const int PB[6] = {0, 1, 0, 1, 2, 0};

    for (int kc = 0; kc < NCH; kc++) {
        if (kc + 1 < NCH) { issue_chunk(kc + 1, (kc + 1) & 1); cpa_wait<1>(); }
        else              { cpa_wait<0>(); }
        __syncthreads();
        const uint32_t sa = sbase + (kc & 1) * STAGE_BYTES;

#pragma unroll
        for (int ks = 0; ks < 2; ks++) {
            uint32_t af[3][4][4];
#pragma unroll
            for (int p = 0; p < 3; p++)
#pragma unroll
                for (int mt = 0; mt < 4; mt++) {
                    const int row = wm * 64 + mt * 16 + (lid & 15);
                    const int gg = ks * 2 + (lid >> 4);
                    ldsm_x4(af[p][mt], sa + p * TILE_BYTES + sw_off(row, gg));
                }
            uint32_t bf[3][2][4];
#pragma unroll
            for (int p = 0; p < 3; p++)
#pragma unroll
                for (int h = 0; h < 2; h++) {
                    const int nsub = (lid >> 4) + h * 2;
                    const int row = wn * 32 + nsub * 8 + (lid & 7);
                    const int gg = ks * 2 + ((lid >> 3) & 1);
                    ldsm_x4(bf[p][h], sa + (3 + p) * TILE_BYTES + sw_off(row, gg));
                }
#pragma unroll
            for (int pr = 0; pr < 6; pr++) {
                const int pa = PA[pr], pb = PB[pr];
#pragma unroll
                for (int mt = 0; mt < 4; mt++)
#pragma unroll
                    for (int nt = 0; nt < 4; nt++)
                        mma16816(acc[mt][nt], af[pa][mt], &bf[pb][nt >> 1][(nt & 1) * 2]);
            }
        }
        __syncthreads();
    }

    // ---------------- epilogue: quantized dist + top-2 ----------------
    const float* ga = g_a + mtile * BM;
    float v1[8], v2[8];
    int i1[8];
#pragma unroll
    for (int i = 0; i < 8; i++) {
        v1[i] = __int_as_float(0x7f800000);
        v2[i] = __int_as_float(0x7f800000);
        i1[i] = 0;
    }

#pragma unroll
    for (int mt = 0; mt < 4; mt++)
#pragma unroll
        for (int rh = 0; rh < 2; rh++) {
            const int r = mt * 2 + rh;
            const float a = ga[wm * 64 + mt * 16 + g + rh * 8];
#pragma unroll
            for (int nt = 0; nt < 4; nt++)
#pragma unroll
                for (int cc = 0; cc < 2; cc++) {
                    const float b = acc[mt][nt][rh * 2 + cc];
                    const int n = ntile * BN + wn * 32 + nt * 8 + 2 * tq + cc;
                    const float d = __fadd_rn(__fadd_rn(a, -__fmul_rn(2.0f, b)), g_c[n]);
                    if (d < v1[r]) { v2[r] = v1[r]; v1[r] = d; i1[r] = n; }
                    else if (d < v2[r]) { v2[r] = d; }
                }
        }

    // merge across the quad (tq) lanes
#pragma unroll
    for (int i = 0; i < 8; i++) {
#pragma unroll
        for (int ofs = 1; ofs <= 2; ofs <<= 1) {
            const float ov1 = __shfl_xor_sync(0xffffffff, v1[i], ofs);
            const int   oi1 = __shfl_xor_sync(0xffffffff, i1[i], ofs);
            const float ov2 = __shfl_xor_sync(0xffffffff, v2[i], ofs);
            float loser;
            if (ov1 < v1[i] || (ov1 == v1[i] && oi1 < i1[i])) {
                loser = v1[i]; v1[i] = ov1; i1[i] = oi1;
            } else {
                loser = ov1;
            }
            v2[i] = fminf(fminf(v2[i], ov2), loser);
        }
    }

    __syncthreads();
    float* cv1 = reinterpret_cast<float*>(smraw);              // [128][4]
    int*   ci1 = reinterpret_cast<int*>(smraw + 2048);         // [128][4]
    float* cv2 = reinterpret_cast<float*>(smraw + 4096);       // [128][4]
    if (tq == 0) {
#pragma unroll
        for (int mt = 0; mt < 4; mt++)
#pragma unroll
            for (int rh = 0; rh < 2; rh++) {
                const int ml = wm * 64 + mt * 16 + g + rh * 8;
                const int r = mt * 2 + rh;
                cv1[ml * 4 + wn] = v1[r];
                ci1[ml * 4 + wn] = i1[r];
                cv2[ml * 4 + wn] = v2[r];
            }
    }
    __syncthreads();
    if (tid < BM) {
        float bv1 = cv1[tid * 4], bv2 = cv2[tid * 4];
        int bi = ci1[tid * 4];
#pragma unroll
        for (int w = 1; w < 4; w++) {
            const float ov1 = cv1[tid * 4 + w], ov2 = cv2[tid * 4 + w];
            const int oi = ci1[tid * 4 + w];
            float loser;
            if (ov1 < bv1 || (ov1 == bv1 && oi < bi)) { loser = bv1; bv1 = ov1; bi = oi; }
            else loser = ov1;
            bv2 = fminf(fminf(bv2, ov2), loser);
        }
        const size_t slot = (size_t)(mtile * BM + tid) * NNT + ntile;
        g_cand1[slot] = ((unsigned long long)__float_as_uint(bv1) << 32) | (unsigned)bi;
        g_cand2[slot] = bv2;
    }
}

// =====================================================================
// Flag: global top-2 per row from 32 CTA candidates; route near-ties to
// the exact-refine list. grid 4096 x 256 (one warp per row).
// =====================================================================
__global__ void flag_kernel() {
    const int tid = threadIdx.x, lane = tid & 31;
    const int m = blockIdx.x * 8 + (tid >> 5);

    unsigned long long key = g_cand1[(size_t)m * NNT + lane];
    float mv2 = g_cand2[(size_t)m * NNT + lane];

    unsigned long long bkey = key;
#pragma unroll
    for (int o = 16; o; o >>= 1) {
        unsigned long long ok = __shfl_xor_sync(0xffffffff, bkey, o);
        if (ok < bkey) bkey = ok;
    }
    const float bv = __uint_as_float((unsigned)(bkey >> 32));
    float cand2 = (key == bkey) ? mv2 : fminf(__uint_as_float((unsigned)(key >> 32)), mv2);
#pragma unroll
    for (int o = 16; o; o >>= 1)
        cand2 = fminf(cand2, __shfl_xor_sync(0xffffffff, cand2, o));

    if (lane == 0) {
        g_idx[m] = (int)(bkey & 0xffffffffu);
        if (__fadd_rn(cand2, -bv) < THRESH) {
            const int pos = atomicAdd(&g_cnt, 1);
            g_list[pos] = m;
        }
    }
}

// =====================================================================
// Refine: exact replication of R2's validated fp32 math for flagged rows.
// fixed grid 256 x 256; each block handles rows strided by gridDim.
// thread t covers n = 1024*j + 4*t + e (ascending), sequential-k fp32 FMA.
// =====================================================================
__global__ void refine_kernel(const float* __restrict__ x) {
    __shared__ float xs[DIM];
    __shared__ float rv[256];
    __shared__ int   rix[256];
    const int t = threadIdx.x;
    const int cnt = g_cnt;

    for (int ri = blockIdx.x; ri < cnt; ri += gridDim.x) {
        const int m = g_list[ri];
        xs[t]       = x[(size_t)m * DIM + t];
        xs[t + 256] = x[(size_t)m * DIM + t + 256];
        __syncthreads();
        const float a = g_a[m];

        float bestv = __int_as_float(0x7f800000);
        int besti = 0;
#pragma unroll
        for (int j = 0; j < 4; j++) {
            const int nb = 1024 * j + 4 * t;
            float b0 = 0.f, b1 = 0.f, b2 = 0.f, b3 = 0.f;
            for (int k = 0; k < DIM; k++) {
                const float xv = xs[k];
                const float4 wv = *reinterpret_cast<const float4*>(
                    g_whatT + (size_t)k * NCODES + nb);
                b0 = __fmaf_rn(xv, wv.x, b0);
                b1 = __fmaf_rn(xv, wv.y, b1);
                b2 = __fmaf_rn(xv, wv.z, b2);
                b3 = __fmaf_rn(xv, wv.w, b3);
            }
            const float4 cv = *reinterpret_cast<const float4*>(g_c + nb);
            float bb[4] = {b0, b1, b2, b3};
            float cc[4] = {cv.x, cv.y, cv.z, cv.w};
#pragma unroll
            for (int e = 0; e < 4; e++) {
                const float d = __fadd_rn(__fadd_rn(a, -__fmul_rn(2.0f, bb[e])), cc[e]);
                if (d < bestv) { bestv = d; besti = nb + e; }
            }
        }
        rv[t] = bestv; rix[t] = besti;
        __syncthreads();
        for (int o = 128; o; o >>= 1) {
            if (t < o) {
                if (rv[t + o] < rv[t] || (rv[t + o] == rv[t] && rix[t + o] < rix[t])) {
                    rv[t] = rv[t + o]; rix[t] = rix[t + o];
                }
            }
            __syncthreads();
        }
        if (t == 0) g_idx[m] = rix[0];
        __syncthreads();
    }
}

// =====================================================================
// Gather + straight-through output + diff accumulation
// =====================================================================
__global__ void gather_kernel(const float* __restrict__ x,
                              const float* __restrict__ ew,
                              float* __restrict__ out) {
    __shared__ double sred[128];
    const int m = blockIdx.x, t = threadIdx.x;
    const int idx = g_idx[m];

    float4 q  = reinterpret_cast<const float4*>(ew + (size_t)idx * DIM)[t];
    float4 xv = reinterpret_cast<const float4*>(x  + (size_t)m * DIM)[t];

    float4 o;
    double s = 0.0;
    {
        float e, q1;
        e = __fadd_rn(q.x, -xv.x); q1 = __fadd_rn(xv.x, e);
        o.x = __fmul_rn(__fadd_rn(q.x, q1), 0.5f); s += (double)e * e;
        e = __fadd_rn(q.y, -xv.y); q1 = __fadd_rn(xv.y, e);
        o.y = __fmul_rn(__fadd_rn(q.y, q1), 0.5f); s += (double)e * e;
        e = __fadd_rn(q.z, -xv.z); q1 = __fadd_rn(xv.z, e);
        o.z = __fmul_rn(__fadd_rn(q.z, q1), 0.5f); s += (double)e * e;
        e = __fadd_rn(q.w, -xv.w); q1 = __fadd_rn(xv.w, e);
        o.w = __fmul_rn(__fadd_rn(q.w, q1), 0.5f); s += (double)e * e;
    }
    reinterpret_cast<float4*>(out)[(size_t)m * (DIM / 4) + t] = o;

    sred[t] = s;
    __syncthreads();
    for (int off = 64; off; off >>= 1) {
        if (t < off) sred[t] += sred[t + off];
        __syncthreads();
    }
    if (t == 0) atomicAdd(&g_diff, sred[0]);
}

__global__ void final_kernel(float* __restrict__ out, int write_scalar) {
    if (write_scalar)
        out[(size_t)M_ROWS * DIM] = (float)(g_diff / (double)((size_t)M_ROWS * DIM));
}

// =====================================================================
extern "C" void kernel_launch(void* const* d_in, const int* in_sizes, int n_in,
                              void* d_out, int out_size) {
    const float* x  = (const float*)d_in[0];
    const float* ew = (const float*)d_in[1];
    if (n_in >= 2 && in_sizes[0] == NCODES * DIM && in_sizes[1] == M_ROWS * DIM) {
        ew = (const float*)d_in[0];
        x  = (const float*)d_in[1];
    }
    float* out = (float*)d_out;

    cudaFuncSetAttribute(mma_topcand_kernel,
                         cudaFuncAttributeMaxDynamicSharedMemorySize, SMEM_BYTES);

    prepw_kernel<<<NCODES, 128>>>(ew);
    prepx_kernel<<<M_ROWS, 128>>>(x);
    mma_topcand_kernel<<<NMT * NNT, TPB, SMEM_BYTES>>>();
    flag_kernel<<<M_ROWS / 8, 256>>>();
    refine_kernel<<<256, 256>>>(x);
    gather_kernel<<<M_ROWS, 128>>>(x, ew, out);
    const int write_scalar = (out_size > M_ROWS * DIM) ? 1 : 0;
    final_kernel<<<1, 1>>>(out, write_scalar);
}

// round 6
// speedup vs baseline: 1.8160x; 1.4048x over previous
#include <cuda_runtime.h>
#include <cuda_bf16.h>
#include <cstdint>
#include <cstddef>

#define M_ROWS 32768
#define DIM    512
#define NCODES 4096

#define BM 128
#define BN 128
#define BK 32
#define NCH (DIM / BK)            // 16 chunks
#define NMT (M_ROWS / BM)         // 256
#define NNT (NCODES / BN)         // 32
#define TPB 256
#define THRESH 1e-3f

#define TILE_BYTES (128 * BK * 2)             // 8192 per plane tile
#define STAGE_BYTES (4 * TILE_BYTES)          // 32768 (2 A planes + 2 B planes)
#define SMEM_BYTES (2 * STAGE_BYTES)          // 65536

// ---------------- device scratch (allocation is forbidden) ----------------
__device__ __align__(128) __nv_bfloat16 g_XA[(size_t)NMT * 2 * 128 * DIM]; // 64MB
__device__ __align__(128) __nv_bfloat16 g_WB[(size_t)NNT * 2 * 128 * DIM]; // 8MB
__device__ __align__(128) float g_whatT[DIM * NCODES];                     // 8MB [k][n]
__device__ float  g_a[M_ROWS];
__device__ float  g_c[NCODES];
__device__ int    g_idx[M_ROWS];
__device__ unsigned long long g_cand1[(size_t)M_ROWS * NNT];  // per (m,ntile) best key
__device__ float  g_cand2[(size_t)M_ROWS * NNT];              // per (m,ntile) 2nd value
__device__ int    g_list[M_ROWS];
__device__ int    g_cnt;
__device__ double g_diff;

// ---------------- PTX helpers (base sm_80 features only) ------------------
__device__ __forceinline__ uint32_t smem_u32(const void* p) {
    uint32_t a;
    asm("{ .reg .u64 t; cvta.to.shared.u64 t, %1; cvt.u32.u64 %0, t; }" : "=r"(a) : "l"(p));
    return a;
}
__device__ __forceinline__ void cpa16(uint32_t dst, const void* src) {
    asm volatile("cp.async.cg.shared.global [%0], [%1], 16;" :: "r"(dst), "l"(src));
}
__device__ __forceinline__ void cpa_commit() { asm volatile("cp.async.commit_group;"); }
template <int N>
__device__ __forceinline__ void cpa_wait() {
    asm volatile("cp.async.wait_group %0;" :: "n"(N));
}
__device__ __forceinline__ void ldsm_x4(uint32_t* r, uint32_t addr) {
    asm volatile("ldmatrix.sync.aligned.m8n8.x4.shared.b16 {%0,%1,%2,%3}, [%4];"
                 : "=r"(r[0]), "=r"(r[1]), "=r"(r[2]), "=r"(r[3]) : "r"(addr));
}
__device__ __forceinline__ void mma16816(float* d, const uint32_t* a, const uint32_t* b) {
    asm volatile(
        "mma.sync.aligned.m16n8k16.row.col.f32.bf16.bf16.f32 "
        "{%0,%1,%2,%3}, {%4,%5,%6,%7}, {%8,%9}, {%0,%1,%2,%3};"
        : "+f"(d[0]), "+f"(d[1]), "+f"(d[2]), "+f"(d[3])
        : "r"(a[0]), "r"(a[1]), "r"(a[2]), "r"(a[3]), "r"(b[0]), "r"(b[1]));
}
__device__ __forceinline__ uint32_t sw_off(int row, int g) {
    return (uint32_t)row * 64u + (uint32_t)((g ^ ((row >> 1) & 3)) << 4);
}
__device__ __forceinline__ void split2(float v, unsigned short& h1, unsigned short& h2) {
    __nv_bfloat16 b1 = __float2bfloat16(v);
    float r1 = v - __bfloat162float(b1);
    __nv_bfloat16 b2 = __float2bfloat16(r1);
    h1 = __bfloat16_as_ushort(b1);
    h2 = __bfloat16_as_ushort(b2);
}
__device__ __forceinline__ uint2 pack4(const unsigned short* h) {
    uint2 q;
    q.x = (uint32_t)h[0] | ((uint32_t)h[1] << 16);
    q.y = (uint32_t)h[2] | ((uint32_t)h[3] << 16);
    return q;
}

// =====================================================================
// Prep W — byte-replicates R2's prep math (128 thr x 4 elems):
// norm = sqrtf((float)double_tree_sum), w = fdiv_rn, c = (float)double tree.
// Writes whatT[k][n] fp32 and 2 bf16 planes (row-major [row][k]).
// =====================================================================
__global__ void prepw_kernel(const float* __restrict__ ew) {
    __shared__ double sred[128];
    const int n = blockIdx.x, t = threadIdx.x;

    float4 v = reinterpret_cast<const float4*>(ew + (size_t)n * DIM)[t];
    double s = (double)v.x * v.x + (double)v.y * v.y +
               (double)v.z * v.z + (double)v.w * v.w;
    sred[t] = s;
    __syncthreads();
    for (int o = 64; o; o >>= 1) { if (t < o) sred[t] += sred[t + o]; __syncthreads(); }
    const float norm = sqrtf((float)sred[0]);
    __syncthreads();

    const float w0 = __fdiv_rn(v.x, norm);
    const float w1 = __fdiv_rn(v.y, norm);
    const float w2 = __fdiv_rn(v.z, norm);
    const float w3 = __fdiv_rn(v.w, norm);

    g_whatT[(size_t)(4 * t + 0) * NCODES + n] = w0;
    g_whatT[(size_t)(4 * t + 1) * NCODES + n] = w1;
    g_whatT[(size_t)(4 * t + 2) * NCODES + n] = w2;
    g_whatT[(size_t)(4 * t + 3) * NCODES + n] = w3;

    double c = (double)w0 * w0 + (double)w1 * w1 +
               (double)w2 * w2 + (double)w3 * w3;
    sred[t] = c;
    __syncthreads();
    for (int o = 64; o; o >>= 1) { if (t < o) sred[t] += sred[t + o]; __syncthreads(); }
    if (t == 0) g_c[n] = (float)sred[0];

    float wv[4] = {w0, w1, w2, w3};
    unsigned short h1[4], h2[4];
#pragma unroll
    for (int i = 0; i < 4; i++) split2(wv[i], h1[i], h2[i]);

    const int ntile = n >> 7, row = n & 127;
    const size_t b0 = (((size_t)ntile * 2 + 0) * 128 + row) * DIM + 4 * t;
    const size_t b1 = (((size_t)ntile * 2 + 1) * 128 + row) * DIM + 4 * t;
    *reinterpret_cast<uint2*>(g_WB + b0) = pack4(h1);
    *reinterpret_cast<uint2*>(g_WB + b1) = pack4(h2);
}

// =====================================================================
// Prep X — a[m] byte-replicates R2's reduction order; 2 bf16 planes.
// =====================================================================
__global__ void prepx_kernel(const float* __restrict__ x) {
    __shared__ double part[4];
    const int m = blockIdx.x, t = threadIdx.x;
    const float* xr = x + (size_t)m * DIM;

    float4 v = reinterpret_cast<const float4*>(xr)[t];
    unsigned short h1[4], h2[4];
    float vv[4] = {v.x, v.y, v.z, v.w};
#pragma unroll
    for (int i = 0; i < 4; i++) split2(vv[i], h1[i], h2[i]);
    const int mtile = m >> 7, row = m & 127;
    const size_t b0 = (((size_t)mtile * 2 + 0) * 128 + row) * DIM + 4 * t;
    const size_t b1 = (((size_t)mtile * 2 + 1) * 128 + row) * DIM + 4 * t;
    *reinterpret_cast<uint2*>(g_XA + b0) = pack4(h1);
    *reinterpret_cast<uint2*>(g_XA + b1) = pack4(h2);

    if (t < 4) {
        const int k0 = t * 128;
        double s0 = 0.0, s1 = 0.0;
        for (int k = 0; k < 128; k += 2) {
            float u0 = xr[k0 + k];
            float u1 = xr[k0 + k + 1];
            s0 += (double)u0 * u0;
            s1 += (double)u1 * u1;
        }
        part[t] = s0 + s1;
    }
    __syncthreads();
    if (t == 0) {
        g_a[m] = (float)(part[0] + part[1] + part[2] + part[3]);
        if (m == 0) { g_cnt = 0; g_diff = 0.0; }
    }
}

// =====================================================================
// HMMA GEMM (2x2 split, 3 pairs) + per-CTA top-2.
// grid = NMT*NNT (ntile fastest), block 256 (8 warps, 2m x 4n).
// =====================================================================
__global__ void __launch_bounds__(TPB, 1) mma_topcand_kernel() {
    extern __shared__ unsigned char smraw[];
    const uint32_t sbase = smem_u32(smraw);

    const int tid = threadIdx.x;
    const int wid = tid >> 5, lid = tid & 31;
    const int wm = wid & 1, wn = wid >> 1;
    const int g = lid >> 2, tq = lid & 3;
    const int ntile = blockIdx.x & (NNT - 1);
    const int mtile = blockIdx.x >> 5;

    const __nv_bfloat16* Aab = g_XA + ((size_t)mtile * 2) * 128 * DIM;
    const __nv_bfloat16* Bab = g_WB + ((size_t)ntile * 2) * 128 * DIM;

    // 4 tiles x 512 granules = 2048 granules / 256 threads = 8 per thread
    auto issue_chunk = [&](int kc, int st) {
        const uint32_t sdst = sbase + st * STAGE_BYTES;
#pragma unroll
        for (int t4 = 0; t4 < 4; t4++) {
            const __nv_bfloat16* src_base =
                (t4 < 2) ? (Aab + (size_t)t4 * 128 * DIM)
                         : (Bab + (size_t)(t4 - 2) * 128 * DIM);
#pragma unroll
            for (int j = 0; j < 2; j++) {
                const int q = tid + j * 256;
                const int row = q >> 2, gg = q & 3;
                cpa16(sdst + t4 * TILE_BYTES + sw_off(row, gg),
                      src_base + (size_t)row * DIM + kc * BK + gg * 8);
            }
        }
        cpa_commit();
    };

    float acc[4][4][4];
#pragma unroll
    for (int i = 0; i < 4; i++)
#pragma unroll
        for (int j = 0; j < 4; j++)
#pragma unroll
            for (int k = 0; k < 4; k++) acc[i][j][k] = 0.0f;

    issue_chunk(0, 0);
    // kept product pairs: (a-plane, b-plane) = (0,0), (0,1), (1,0)
    const int PA[3] = {0, 0, 1};
    const int PB[3] = {0, 1, 0};

    for (int kc = 0; kc < NCH; kc++) {
        if (kc + 1 < NCH) { issue_chunk(kc + 1, (kc + 1) & 1); cpa_wait<1>(); }
        else              { cpa_wait<0>(); }
        __syncthreads();
        const uint32_t sa = sbase + (kc & 1) * STAGE_BYTES;

#pragma unroll
        for (int ks = 0; ks < 2; ks++) {
            uint32_t af[2][4][4];
#pragma unroll
            for (int p = 0; p < 2; p++)
#pragma unroll
                for (int mt = 0; mt < 4; mt++) {
                    const int row = wm * 64 + mt * 16 + (lid & 15);
                    const int gg = ks * 2 + (lid >> 4);
                    ldsm_x4(af[p][mt], sa + p * TILE_BYTES + sw_off(row, gg));
                }
            uint32_t bf[2][2][4];
#pragma unroll
            for (int p = 0; p < 2; p++)
#pragma unroll
                for (int h = 0; h < 2; h++) {
                    const int nsub = (lid >> 4) + h * 2;
                    const int row = wn * 32 + nsub * 8 + (lid & 7);
                    const int gg = ks * 2 + ((lid >> 3) & 1);
                    ldsm_x4(bf[p][h], sa + (2 + p) * TILE_BYTES + sw_off(row, gg));
                }
#pragma unroll
            for (int pr = 0; pr < 3; pr++) {
                const int pa = PA[pr], pb = PB[pr];
#pragma unroll
                for (int mt = 0; mt < 4; mt++)
#pragma unroll
                    for (int nt = 0; nt < 4; nt++)
                        mma16816(acc[mt][nt], af[pa][mt], &bf[pb][nt >> 1][(nt & 1) * 2]);
            }
        }
        __syncthreads();
    }

    // ---------------- epilogue: quantized dist + top-2 ----------------
    const float* ga = g_a + mtile * BM;
    float v1[8], v2[8];
    int i1[8];
#pragma unroll
    for (int i = 0; i < 8; i++) {
        v1[i] = __int_as_float(0x7f800000);
        v2[i] = __int_as_float(0x7f800000);
        i1[i] = 0;
    }

#pragma unroll
    for (int mt = 0; mt < 4; mt++)
#pragma unroll
        for (int rh = 0; rh < 2; rh++) {
            const int r = mt * 2 + rh;
            const float a = ga[wm * 64 + mt * 16 + g + rh * 8];
#pragma unroll
            for (int nt = 0; nt < 4; nt++)
#pragma unroll
                for (int cc = 0; cc < 2; cc++) {
                    const float b = acc[mt][nt][rh * 2 + cc];
                    const int n = ntile * BN + wn * 32 + nt * 8 + 2 * tq + cc;
                    const float d = __fadd_rn(__fadd_rn(a, -__fmul_rn(2.0f, b)), g_c[n]);
                    if (d < v1[r]) { v2[r] = v1[r]; v1[r] = d; i1[r] = n; }
                    else if (d < v2[r]) { v2[r] = d; }
                }
        }

    // merge across the quad (tq) lanes
#pragma unroll
    for (int i = 0; i < 8; i++) {
#pragma unroll
        for (int ofs = 1; ofs <= 2; ofs <<= 1) {
            const float ov1 = __shfl_xor_sync(0xffffffff, v1[i], ofs);
            const int   oi1 = __shfl_xor_sync(0xffffffff, i1[i], ofs);
            const float ov2 = __shfl_xor_sync(0xffffffff, v2[i], ofs);
            float loser;
            if (ov1 < v1[i] || (ov1 == v1[i] && oi1 < i1[i])) {
                loser = v1[i]; v1[i] = ov1; i1[i] = oi1;
            } else {
                loser = ov1;
            }
            v2[i] = fminf(fminf(v2[i], ov2), loser);
        }
    }

    __syncthreads();
    float* cv1 = reinterpret_cast<float*>(smraw);              // [128][4]
    int*   ci1 = reinterpret_cast<int*>(smraw + 2048);         // [128][4]
    float* cv2 = reinterpret_cast<float*>(smraw + 4096);       // [128][4]
    if (tq == 0) {
#pragma unroll
        for (int mt = 0; mt < 4; mt++)
#pragma unroll
            for (int rh = 0; rh < 2; rh++) {
                const int ml = wm * 64 + mt * 16 + g + rh * 8;
                const int r = mt * 2 + rh;
                cv1[ml * 4 + wn] = v1[r];
                ci1[ml * 4 + wn] = i1[r];
                cv2[ml * 4 + wn] = v2[r];
            }
    }
    __syncthreads();
    if (tid < BM) {
        float bv1 = cv1[tid * 4], bv2 = cv2[tid * 4];
        int bi = ci1[tid * 4];
#pragma unroll
        for (int w = 1; w < 4; w++) {
            const float ov1 = cv1[tid * 4 + w], ov2 = cv2[tid * 4 + w];
            const int oi = ci1[tid * 4 + w];
            float loser;
            if (ov1 < bv1 || (ov1 == bv1 && oi < bi)) { loser = bv1; bv1 = ov1; bi = oi; }
            else loser = ov1;
            bv2 = fminf(fminf(bv2, ov2), loser);
        }
        const size_t slot = (size_t)(mtile * BM + tid) * NNT + ntile;
        g_cand1[slot] = ((unsigned long long)__float_as_uint(bv1) << 32) | (unsigned)bi;
        g_cand2[slot] = bv2;
    }
}

// =====================================================================
// Flag: global top-2 per row; route near-ties (gap < THRESH) to refine.
// =====================================================================
__global__ void flag_kernel() {
    const int tid = threadIdx.x, lane = tid & 31;
    const int m = blockIdx.x * 8 + (tid >> 5);

    unsigned long long key = g_cand1[(size_t)m * NNT + lane];
    float mv2 = g_cand2[(size_t)m * NNT + lane];

    unsigned long long bkey = key;
#pragma unroll
    for (int o = 16; o; o >>= 1) {
        unsigned long long ok = __shfl_xor_sync(0xffffffff, bkey, o);
        if (ok < bkey) bkey = ok;
    }
    const float bv = __uint_as_float((unsigned)(bkey >> 32));
    float cand2 = (key == bkey) ? mv2 : fminf(__uint_as_float((unsigned)(key >> 32)), mv2);
#pragma unroll
    for (int o = 16; o; o >>= 1)
        cand2 = fminf(cand2, __shfl_xor_sync(0xffffffff, cand2, o));

    if (lane == 0) {
        g_idx[m] = (int)(bkey & 0xffffffffu);
        if (__fadd_rn(cand2, -bv) < THRESH) {
            const int pos = atomicAdd(&g_cnt, 1);
            g_list[pos] = m;
        }
    }
}

// =====================================================================
// Refine: exact replication of R2's validated fp32 math for flagged rows.
// =====================================================================
__global__ void refine_kernel(const float* __restrict__ x) {
    __shared__ float xs[DIM];
    __shared__ float rv[256];
    __shared__ int   rix[256];
    const int t = threadIdx.x;
    const int cnt = g_cnt;

    for (int ri = blockIdx.x; ri < cnt; ri += gridDim.x) {
        const int m = g_list[ri];
        xs[t]       = x[(size_t)m * DIM + t];
        xs[t + 256] = x[(size_t)m * DIM + t + 256];
        __syncthreads();
        const float a = g_a[m];

        float bestv = __int_as_float(0x7f800000);
        int besti = 0;
#pragma unroll
        for (int j = 0; j < 4; j++) {
            const int nb = 1024 * j + 4 * t;
            float b0 = 0.f, b1 = 0.f, b2 = 0.f, b3 = 0.f;
            for (int k = 0; k < DIM; k++) {
                const float xv = xs[k];
                const float4 wv = *reinterpret_cast<const float4*>(
                    g_whatT + (size_t)k * NCODES + nb);
                b0 = __fmaf_rn(xv, wv.x, b0);
                b1 = __fmaf_rn(xv, wv.y, b1);
                b2 = __fmaf_rn(xv, wv.z, b2);
                b3 = __fmaf_rn(xv, wv.w, b3);
            }
            const float4 cv = *reinterpret_cast<const float4*>(g_c + nb);
            float bb[4] = {b0, b1, b2, b3};
            float cc[4] = {cv.x, cv.y, cv.z, cv.w};
#pragma unroll
            for (int e = 0; e < 4; e++) {
                const float d = __fadd_rn(__fadd_rn(a, -__fmul_rn(2.0f, bb[e])), cc[e]);
                if (d < bestv) { bestv = d; besti = nb + e; }
            }
        }
        rv[t] = bestv; rix[t] = besti;
        __syncthreads();
        for (int o = 128; o; o >>= 1) {
            if (t < o) {
                if (rv[t + o] < rv[t] || (rv[t + o] == rv[t] && rix[t + o] < rix[t])) {
                    rv[t] = rv[t + o]; rix[t] = rix[t + o];
                }
            }
            __syncthreads();
        }
        if (t == 0) g_idx[m] = rix[0];
        __syncthreads();
    }
}

// =====================================================================
// Gather + straight-through output + diff accumulation
// =====================================================================
__global__ void gather_kernel(const float* __restrict__ x,
                              const float* __restrict__ ew,
                              float* __restrict__ out) {
    __shared__ double sred[128];
    const int m = blockIdx.x, t = threadIdx.x;
    const int idx = g_idx[m];

    float4 q  = reinterpret_cast<const float4*>(ew + (size_t)idx * DIM)[t];
    float4 xv = reinterpret_cast<const float4*>(x  + (size_t)m * DIM)[t];

    float4 o;
    double s = 0.0;
    {
        float e, q1;
        e = __fadd_rn(q.x, -xv.x); q1 = __fadd_rn(xv.x, e);
        o.x = __fmul_rn(__fadd_rn(q.x, q1), 0.5f); s += (double)e * e;
        e = __fadd_rn(q.y, -xv.y); q1 = __fadd_rn(xv.y, e);
        o.y = __fmul_rn(__fadd_rn(q.y, q1), 0.5f); s += (double)e * e;
        e = __fadd_rn(q.z, -xv.z); q1 = __fadd_rn(xv.z, e);
        o.z = __fmul_rn(__fadd_rn(q.z, q1), 0.5f); s += (double)e * e;
        e = __fadd_rn(q.w, -xv.w); q1 = __fadd_rn(xv.w, e);
        o.w = __fmul_rn(__fadd_rn(q.w, q1), 0.5f); s += (double)e * e;
    }
    reinterpret_cast<float4*>(out)[(size_t)m * (DIM / 4) + t] = o;

    sred[t] = s;
    __syncthreads();
    for (int off = 64; off; off >>= 1) {
        if (t < off) sred[t] += sred[t + off];
        __syncthreads();
    }
    if (t == 0) atomicAdd(&g_diff, sred[0]);
}

__global__ void final_kernel(float* __restrict__ out, int write_scalar) {
    if (write_scalar)
        out[(size_t)M_ROWS * DIM] = (float)(g_diff / (double)((size_t)M_ROWS * DIM));
}

// =====================================================================
extern "C" void kernel_launch(void* const* d_in, const int* in_sizes, int n_in,
                              void* d_out, int out_size) {
    const float* x  = (const float*)d_in[0];
    const float* ew = (const float*)d_in[1];
    if (n_in >= 2 && in_sizes[0] == NCODES * DIM && in_sizes[1] == M_ROWS * DIM) {
        ew = (const float*)d_in[0];
        x  = (const float*)d_in[1];
    }
    float* out = (float*)d_out;

    cudaFuncSetAttribute(mma_topcand_kernel,
                         cudaFuncAttributeMaxDynamicSharedMemorySize, SMEM_BYTES);

    prepw_kernel<<<NCODES, 128>>>(ew);
    prepx_kernel<<<M_ROWS, 128>>>(x);
    mma_topcand_kernel<<<NMT * NNT, TPB, SMEM_BYTES>>>();
    flag_kernel<<<M_ROWS / 8, 256>>>();
    refine_kernel<<<256, 256>>>(x);
    gather_kernel<<<M_ROWS, 128>>>(x, ew, out);
    const int write_scalar = (out_size > M_ROWS * DIM) ? 1 : 0;
    final_kernel<<<1, 1>>>(out, write_scalar);
}

// round 7
// speedup vs baseline: 3.0521x; 1.6807x over previous
#include <cuda_runtime.h>
#include <cuda_fp16.h>
#include <cstdint>
#include <cstddef>

#define M_ROWS 32768
#define DIM    512
#define NCODES 4096

#define BM 128
#define BN 128
#define BK 32
#define NCH (DIM / BK)            // 16 chunks
#define NMT (M_ROWS / BM)         // 256
#define NNT (NCODES / BN)         // 32
#define TPB 256
#define THRESH 1e-2f

#define TILE_BYTES (128 * BK * 2)             // 8192 per fp16 tile
#define STAGE_BYTES (2 * TILE_BYTES)          // 16384 (1 A tile + 1 B tile)
#define SMEM_BYTES (2 * STAGE_BYTES)          // 32768

// ---------------- device scratch (allocation is forbidden) ----------------
__device__ __align__(128) __half g_XH[(size_t)NMT * 128 * DIM];  // 32MB fp16 x
__device__ __align__(128) __half g_WH[(size_t)NNT * 128 * DIM];  // 4MB fp16 w_hat
__device__ __align__(128) float g_whatT[DIM * NCODES];           // 8MB fp32 [k][n]
__device__ float  g_a[M_ROWS];
__device__ float  g_c[NCODES];
__device__ int    g_idx[M_ROWS];
__device__ unsigned long long g_cand1[(size_t)M_ROWS * NNT];
__device__ float  g_cand2[(size_t)M_ROWS * NNT];
__device__ unsigned long long g_key2[M_ROWS];  // refine result keys
__device__ int    g_list[M_ROWS];
__device__ int    g_cnt;
__device__ double g_diff;

// ---------------- PTX helpers (base sm_80 features only) ------------------
__device__ __forceinline__ uint32_t smem_u32(const void* p) {
    uint32_t a;
    asm("{ .reg .u64 t; cvta.to.shared.u64 t, %1; cvt.u32.u64 %0, t; }" : "=r"(a) : "l"(p));
    return a;
}
__device__ __forceinline__ void cpa16(uint32_t dst, const void* src) {
    asm volatile("cp.async.cg.shared.global [%0], [%1], 16;" :: "r"(dst), "l"(src));
}
__device__ __forceinline__ void cpa_commit() { asm volatile("cp.async.commit_group;"); }
template <int N>
__device__ __forceinline__ void cpa_wait() {
    asm volatile("cp.async.wait_group %0;" :: "n"(N));
}
__device__ __forceinline__ void ldsm_x4(uint32_t* r, uint32_t addr) {
    asm volatile("ldmatrix.sync.aligned.m8n8.x4.shared.b16 {%0,%1,%2,%3}, [%4];"
                 : "=r"(r[0]), "=r"(r[1]), "=r"(r[2]), "=r"(r[3]) : "r"(addr));
}
__device__ __forceinline__ void mma16816(float* d, const uint32_t* a, const uint32_t* b) {
    asm volatile(
        "mma.sync.aligned.m16n8k16.row.col.f32.f16.f16.f32 "
        "{%0,%1,%2,%3}, {%4,%5,%6,%7}, {%8,%9}, {%0,%1,%2,%3};"
        : "+f"(d[0]), "+f"(d[1]), "+f"(d[2]), "+f"(d[3])
        : "r"(a[0]), "r"(a[1]), "r"(a[2]), "r"(a[3]), "r"(b[0]), "r"(b[1]));
}
__device__ __forceinline__ uint32_t sw_off(int row, int g) {
    return (uint32_t)row * 64u + (uint32_t)((g ^ ((row >> 1) & 3)) << 4);
}
__device__ __forceinline__ uint2 pack4h(const float* v) {
    unsigned short h[4];
#pragma unroll
    for (int i = 0; i < 4; i++) h[i] = __half_as_ushort(__float2half_rn(v[i]));
    uint2 q;
    q.x = (uint32_t)h[0] | ((uint32_t)h[1] << 16);
    q.y = (uint32_t)h[2] | ((uint32_t)h[3] << 16);
    return q;
}

// =====================================================================
// Prep W — R2-replicated math: norm = sqrtf((float)double_tree_sum),
// w = fdiv_rn, c = (float)double tree. Writes whatT fp32 + 1 fp16 plane.
// =====================================================================
__global__ void prepw_kernel(const float* __restrict__ ew) {
    __shared__ double sred[128];
    const int n = blockIdx.x, t = threadIdx.x;

    float4 v = reinterpret_cast<const float4*>(ew + (size_t)n * DIM)[t];
    double s = (double)v.x * v.x + (double)v.y * v.y +
               (double)v.z * v.z + (double)v.w * v.w;
    sred[t] = s;
    __syncthreads();
    for (int o = 64; o; o >>= 1) { if (t < o) sred[t] += sred[t + o]; __syncthreads(); }
    const float norm = sqrtf((float)sred[0]);
    __syncthreads();

    const float w0 = __fdiv_rn(v.x, norm);
    const float w1 = __fdiv_rn(v.y, norm);
    const float w2 = __fdiv_rn(v.z, norm);
    const float w3 = __fdiv_rn(v.w, norm);

    g_whatT[(size_t)(4 * t + 0) * NCODES + n] = w0;
    g_whatT[(size_t)(4 * t + 1) * NCODES + n] = w1;
    g_whatT[(size_t)(4 * t + 2) * NCODES + n] = w2;
    g_whatT[(size_t)(4 * t + 3) * NCODES + n] = w3;

    double c = (double)w0 * w0 + (double)w1 * w1 +
               (double)w2 * w2 + (double)w3 * w3;
    sred[t] = c;
    __syncthreads();
    for (int o = 64; o; o >>= 1) { if (t < o) sred[t] += sred[t + o]; __syncthreads(); }
    if (t == 0) g_c[n] = (float)sred[0];

    float wv[4] = {w0, w1, w2, w3};
    const int ntile = n >> 7, row = n & 127;
    *reinterpret_cast<uint2*>(g_WH + ((size_t)(ntile * 128 + row)) * DIM + 4 * t) = pack4h(wv);
}

// =====================================================================
// Prep X — a[m] with R2's reduction order; 1 fp16 plane; init counters.
// =====================================================================
__global__ void prepx_kernel(const float* __restrict__ x) {
    __shared__ double part[4];
    const int m = blockIdx.x, t = threadIdx.x;
    const float* xr = x + (size_t)m * DIM;

    float4 v = reinterpret_cast<const float4*>(xr)[t];
    float vv[4] = {v.x, v.y, v.z, v.w};
    const int mtile = m >> 7, row = m & 127;
    *reinterpret_cast<uint2*>(g_XH + ((size_t)(mtile * 128 + row)) * DIM + 4 * t) = pack4h(vv);

    if (t < 4) {
        const int k0 = t * 128;
        double s0 = 0.0, s1 = 0.0;
        for (int k = 0; k < 128; k += 2) {
            float u0 = xr[k0 + k];
            float u1 = xr[k0 + k + 1];
            s0 += (double)u0 * u0;
            s1 += (double)u1 * u1;
        }
        part[t] = s0 + s1;
    }
    __syncthreads();
    if (t == 0) {
        g_a[m] = (float)(part[0] + part[1] + part[2] + part[3]);
        if (m == 0) { g_cnt = 0; g_diff = 0.0; }
    }
}

// =====================================================================
// HMMA GEMM (single fp16 pair) + per-CTA top-2.
// grid = NMT*NNT (ntile fastest), block 256 (8 warps, 2m x 4n), 2 CTAs/SM.
// =====================================================================
__global__ void __launch_bounds__(TPB, 2) mma_topcand_kernel() {
    extern __shared__ unsigned char smraw[];
    const uint32_t sbase = smem_u32(smraw);

    const int tid = threadIdx.x;
    const int wid = tid >> 5, lid = tid & 31;
    const int wm = wid & 1, wn = wid >> 1;
    const int g = lid >> 2, tq = lid & 3;
    const int ntile = blockIdx.x & (NNT - 1);
    const int mtile = blockIdx.x >> 5;

    const __half* Aab = g_XH + (size_t)mtile * 128 * DIM;
    const __half* Bab = g_WH + (size_t)ntile * 128 * DIM;

    // 2 tiles x 512 granules = 1024 granules / 256 threads = 4 per thread
    auto issue_chunk = [&](int kc, int st) {
        const uint32_t sdst = sbase + st * STAGE_BYTES;
#pragma unroll
        for (int t2 = 0; t2 < 2; t2++) {
            const __half* src_base = (t2 == 0) ? Aab : Bab;
#pragma unroll
            for (int j = 0; j < 2; j++) {
                const int q = tid + j * 256;
                const int row = q >> 2, gg = q & 3;
                cpa16(sdst + t2 * TILE_BYTES + sw_off(row, gg),
                      src_base + (size_t)row * DIM + kc * BK + gg * 8);
            }
        }
        cpa_commit();
    };

    float acc[4][4][4];
#pragma unroll
    for (int i = 0; i < 4; i++)
#pragma unroll
        for (int j = 0; j < 4; j++)
#pragma unroll
            for (int k = 0; k < 4; k++) acc[i][j][k] = 0.0f;

    issue_chunk(0, 0);

    for (int kc = 0; kc < NCH; kc++) {
        if (kc + 1 < NCH) { issue_chunk(kc + 1, (kc + 1) & 1); cpa_wait<1>(); }
        else              { cpa_wait<0>(); }
        __syncthreads();
        const uint32_t sa = sbase + (kc & 1) * STAGE_BYTES;

#pragma unroll
        for (int ks = 0; ks < 2; ks++) {
            uint32_t af[4][4];
#pragma unroll
            for (int mt = 0; mt < 4; mt++) {
                const int row = wm * 64 + mt * 16 + (lid & 15);
                const int gg = ks * 2 + (lid >> 4);
                ldsm_x4(af[mt], sa + sw_off(row, gg));
            }
            uint32_t bf[2][4];
#pragma unroll
            for (int h = 0; h < 2; h++) {
                const int nsub = (lid >> 4) + h * 2;
                const int row = wn * 32 + nsub * 8 + (lid & 7);
                const int gg = ks * 2 + ((lid >> 3) & 1);
                ldsm_x4(bf[h], sa + TILE_BYTES + sw_off(row, gg));
            }
#pragma unroll
            for (int mt = 0; mt < 4; mt++)
#pragma unroll
                for (int nt = 0; nt < 4; nt++)
                    mma16816(acc[mt][nt], af[mt], &bf[nt >> 1][(nt & 1) * 2]);
        }
        __syncthreads();
    }

    // ---------------- epilogue: dist + top-2 ----------------
    const float* ga = g_a + mtile * BM;
    float v1[8], v2[8];
    int i1[8];
#pragma unroll
    for (int i = 0; i < 8; i++) {
        v1[i] = __int_as_float(0x7f800000);
        v2[i] = __int_as_float(0x7f800000);
        i1[i] = 0;
    }

#pragma unroll
    for (int mt = 0; mt < 4; mt++)
#pragma unroll
        for (int rh = 0; rh < 2; rh++) {
            const int r = mt * 2 + rh;
            const float a = ga[wm * 64 + mt * 16 + g + rh * 8];
#pragma unroll
            for (int nt = 0; nt < 4; nt++)
#pragma unroll
                for (int cc = 0; cc < 2; cc++) {
                    const float b = acc[mt][nt][rh * 2 + cc];
                    const int n = ntile * BN + wn * 32 + nt * 8 + 2 * tq + cc;
                    const float d = __fadd_rn(__fadd_rn(a, -__fmul_rn(2.0f, b)), g_c[n]);
                    if (d < v1[r]) { v2[r] = v1[r]; v1[r] = d; i1[r] = n; }
                    else if (d < v2[r]) { v2[r] = d; }
                }
        }

#pragma unroll
    for (int i = 0; i < 8; i++) {
#pragma unroll
        for (int ofs = 1; ofs <= 2; ofs <<= 1) {
            const float ov1 = __shfl_xor_sync(0xffffffff, v1[i], ofs);
            const int   oi1 = __shfl_xor_sync(0xffffffff, i1[i], ofs);
            const float ov2 = __shfl_xor_sync(0xffffffff, v2[i], ofs);
            float loser;
            if (ov1 < v1[i] || (ov1 == v1[i] && oi1 < i1[i])) {
                loser = v1[i]; v1[i] = ov1; i1[i] = oi1;
            } else {
                loser = ov1;
            }
            v2[i] = fminf(fminf(v2[i], ov2), loser);
        }
    }

    __syncthreads();
    float* cv1 = reinterpret_cast<float*>(smraw);              // [128][4]
    int*   ci1 = reinterpret_cast<int*>(smraw + 2048);
    float* cv2 = reinterpret_cast<float*>(smraw + 4096);
    if (tq == 0) {
#pragma unroll
        for (int mt = 0; mt < 4; mt++)
#pragma unroll
            for (int rh = 0; rh < 2; rh++) {
                const int ml = wm * 64 + mt * 16 + g + rh * 8;
                const int r = mt * 2 + rh;
                cv1[ml * 4 + wn] = v1[r];
                ci1[ml * 4 + wn] = i1[r];
                cv2[ml * 4 + wn] = v2[r];
            }
    }
    __syncthreads();
    if (tid < BM) {
        float bv1 = cv1[tid * 4], bv2 = cv2[tid * 4];
        int bi = ci1[tid * 4];
#pragma unroll
        for (int w = 1; w < 4; w++) {
            const float ov1 = cv1[tid * 4 + w], ov2 = cv2[tid * 4 + w];
            const int oi = ci1[tid * 4 + w];
            float loser;
            if (ov1 < bv1 || (ov1 == bv1 && oi < bi)) { loser = bv1; bv1 = ov1; bi = oi; }
            else loser = ov1;
            bv2 = fminf(fminf(bv2, ov2), loser);
        }
        const size_t slot = (size_t)(mtile * BM + tid) * NNT + ntile;
        g_cand1[slot] = ((unsigned long long)__float_as_uint(bv1) << 32) | (unsigned)bi;
        g_cand2[slot] = bv2;
    }
}

// =====================================================================
// Flag: global top-2 per row; near-ties (gap < THRESH) -> refine list.
// =====================================================================
__global__ void flag_kernel() {
    const int tid = threadIdx.x, lane = tid & 31;
    const int m = blockIdx.x * 8 + (tid >> 5);

    unsigned long long key = g_cand1[(size_t)m * NNT + lane];
    float mv2 = g_cand2[(size_t)m * NNT + lane];

    unsigned long long bkey = key;
#pragma unroll
    for (int o = 16; o; o >>= 1) {
        unsigned long long ok = __shfl_xor_sync(0xffffffff, bkey, o);
        if (ok < bkey) bkey = ok;
    }
    const float bv = __uint_as_float((unsigned)(bkey >> 32));
    float cand2 = (key == bkey) ? mv2 : fminf(__uint_as_float((unsigned)(key >> 32)), mv2);
#pragma unroll
    for (int o = 16; o; o >>= 1)
        cand2 = fminf(cand2, __shfl_xor_sync(0xffffffff, cand2, o));

    if (lane == 0) {
        g_idx[m] = (int)(bkey & 0xffffffffu);
        if (__fadd_rn(cand2, -bv) < THRESH) {
            g_key2[m] = ~0ull;
            const int pos = atomicAdd(&g_cnt, 1);
            g_list[pos] = m;
        }
    }
}

// =====================================================================
// Refine: exact R2-replicated fp32 math, tiled as (32 n-slabs x rowgroups
// of 64). Per CTA: 64 flagged rows SMEM-resident, slab of 128 codes.
// dist values identical to R2 (sequential-k fma chain per (m,n)); global
// merge via packed (dist_bits, idx) atomicMin => value-then-lowest-index.
// =====================================================================
__global__ void __launch_bounds__(256, 1) refine_kernel(const float* __restrict__ x) {
    __shared__ float xsT[DIM * 64];   // [k][j] 128KB
    __shared__ int   mlist[64];
    __shared__ float a_s[64];
    const int tid = threadIdx.x;
    const int nt = blockIdx.x & 31;
    const int rg0 = blockIdx.x >> 5;   // 0..7
    const int cnt = g_cnt;

    for (int rg = rg0; rg * 64 < cnt; rg += 8) {
        const int nrows = min(64, cnt - rg * 64);
        if (tid < 64) {
            const int src = rg * 64 + ((tid < nrows) ? tid : 0);
            const int mm = g_list[src];
            mlist[tid] = mm;
            a_s[tid] = g_a[mm];
        }
        __syncthreads();
        for (int idx = tid; idx < 64 * DIM; idx += 256) {
            const int j = idx & 63, k = idx >> 6;
            xsT[k * 64 + j] = x[(size_t)mlist[j] * DIM + k];
        }
        __syncthreads();

        const int tm = tid & 15;           // 4 rows each
        const int tn = tid >> 4;           // 16 groups x 8 codes
        const int nb = nt * 128 + tn * 8;

        float acc[4][8];
#pragma unroll
        for (int i = 0; i < 4; i++)
#pragma unroll
            for (int e = 0; e < 8; e++) acc[i][e] = 0.0f;

#pragma unroll 4
        for (int k = 0; k < DIM; k++) {
            const float4 xv = *reinterpret_cast<const float4*>(&xsT[k * 64 + tm * 4]);
            const float4 wa = *reinterpret_cast<const float4*>(g_whatT + (size_t)k * NCODES + nb);
            const float4 wb = *reinterpret_cast<const float4*>(g_whatT + (size_t)k * NCODES + nb + 4);
            const float xr[4] = {xv.x, xv.y, xv.z, xv.w};
            const float wr[8] = {wa.x, wa.y, wa.z, wa.w, wb.x, wb.y, wb.z, wb.w};
#pragma unroll
            for (int i = 0; i < 4; i++)
#pragma unroll
                for (int e = 0; e < 8; e++)
                    acc[i][e] = __fmaf_rn(xr[i], wr[e], acc[i][e]);
        }

        // per-thread best over its 8 codes for each of its 4 rows
        float bv[4];
        int bi[4];
#pragma unroll
        for (int i = 0; i < 4; i++) {
            const float a = a_s[tm * 4 + i];
            bv[i] = __int_as_float(0x7f800000);
            bi[i] = NCODES;
#pragma unroll
            for (int e = 0; e < 8; e++) {
                const float d = __fadd_rn(__fadd_rn(a, -__fmul_rn(2.0f, acc[i][e])),
                                          g_c[nb + e]);
                if (d < bv[i]) { bv[i] = d; bi[i] = nb + e; }
            }
        }
        __syncthreads();  // xsT reads done; reuse as reduction scratch
        float* rv = xsT;                              // [64][16]
        int*   ri = reinterpret_cast<int*>(xsT + 64 * 16);
#pragma unroll
        for (int i = 0; i < 4; i++) {
            rv[(tm * 4 + i) * 16 + tn] = bv[i];
            ri[(tm * 4 + i) * 16 + tn] = bi[i];
        }
        __syncthreads();
        if (tid < nrows) {
            float v = rv[tid * 16];
            int ix = ri[tid * 16];
#pragma unroll
            for (int w = 1; w < 16; w++) {
                const float ov = rv[tid * 16 + w];
                const int oi = ri[tid * 16 + w];
                if (ov < v || (ov == v && oi < ix)) { v = ov; ix = oi; }
            }
            atomicMin(&g_key2[mlist[tid]],
                      ((unsigned long long)__float_as_uint(v) << 32) | (unsigned)ix);
        }
        __syncthreads();
    }
}

// apply refined indices
__global__ void apply_kernel() {
    const int cnt = g_cnt;
    for (int i = blockIdx.x * 256 + threadIdx.x; i < cnt; i += gridDim.x * 256) {
        const int m = g_list[i];
        g_idx[m] = (int)(g_key2[m] & 0xffffffffu);
    }
}

// =====================================================================
// Gather + straight-through output + diff accumulation
// =====================================================================
__global__ void gather_kernel(const float* __restrict__ x,
                              const float* __restrict__ ew,
                              float* __restrict__ out) {
    __shared__ double sred[128];
    const int m = blockIdx.x, t = threadIdx.x;
    const int idx = g_idx[m];

    float4 q  = reinterpret_cast<const float4*>(ew + (size_t)idx * DIM)[t];
    float4 xv = reinterpret_cast<const float4*>(x  + (size_t)m * DIM)[t];

    float4 o;
    double s = 0.0;
    {
        float e, q1;
        e = __fadd_rn(q.x, -xv.x); q1 = __fadd_rn(xv.x, e);
        o.x = __fmul_rn(__fadd_rn(q.x, q1), 0.5f); s += (double)e * e;
        e = __fadd_rn(q.y, -xv.y); q1 = __fadd_rn(xv.y, e);
        o.y = __fmul_rn(__fadd_rn(q.y, q1), 0.5f); s += (double)e * e;
        e = __fadd_rn(q.z, -xv.z); q1 = __fadd_rn(xv.z, e);
        o.z = __fmul_rn(__fadd_rn(q.z, q1), 0.5f); s += (double)e * e;
        e = __fadd_rn(q.w, -xv.w); q1 = __fadd_rn(xv.w, e);
        o.w = __fmul_rn(__fadd_rn(q.w, q1), 0.5f); s += (double)e * e;
    }
    reinterpret_cast<float4*>(out)[(size_t)m * (DIM / 4) + t] = o;

    sred[t] = s;
    __syncthreads();
    for (int off = 64; off; off >>= 1) {
        if (t < off) sred[t] += sred[t + off];
        __syncthreads();
    }
    if (t == 0) atomicAdd(&g_diff, sred[0]);
}

__global__ void final_kernel(float* __restrict__ out, int write_scalar) {
    if (write_scalar)
        out[(size_t)M_ROWS * DIM] = (float)(g_diff / (double)((size_t)M_ROWS * DIM));
}

// =====================================================================
extern "C" void kernel_launch(void* const* d_in, const int* in_sizes, int n_in,
                              void* d_out, int out_size) {
    const float* x  = (const float*)d_in[0];
    const float* ew = (const float*)d_in[1];
    if (n_in >= 2 && in_sizes[0] == NCODES * DIM && in_sizes[1] == M_ROWS * DIM) {
        ew = (const float*)d_in[0];
        x  = (const float*)d_in[1];
    }
    float* out = (float*)d_out;

    cudaFuncSetAttribute(mma_topcand_kernel,
                         cudaFuncAttributeMaxDynamicSharedMemorySize, SMEM_BYTES);

    prepw_kernel<<<NCODES, 128>>>(ew);
    prepx_kernel<<<M_ROWS, 128>>>(x);
    mma_topcand_kernel<<<NMT * NNT, TPB, SMEM_BYTES>>>();
    flag_kernel<<<M_ROWS / 8, 256>>>();
    refine_kernel<<<256, 256>>>(x);
    apply_kernel<<<32, 256>>>();
    gather_kernel<<<M_ROWS, 128>>>(x, ew, out);
    const int write_scalar = (out_size > M_ROWS * DIM) ? 1 : 0;
    final_kernel<<<1, 1>>>(out, write_scalar);
}